// round 1
// baseline (speedup 1.0000x reference)
#include <cuda_runtime.h>
#include <math.h>
#include <stdint.h>

// Problem constants
// x: [2, 2048, 768]; heads=12, head_dim=64, mlp=3072
#define ROWS   4096           // B*N
#define CDIM   768
#define QKVDIM 2304
#define HID    3072
#define NHEAD  12
#define HDIM   64
#define SEQ    2048

// ---------------- scratch (device globals: no allocs allowed) ----------------
__device__ float g_h[ROWS * CDIM];            // LN output (reused for LN1/LN2)
__device__ float g_qkv[ROWS * QKVDIM];        // qkv projection
__device__ float g_S[(long long)24 * SEQ * SEQ]; // attention scores / probs (402MB)
__device__ float g_attn[ROWS * CDIM];         // attention output (B,N,C)
__device__ float g_x1[ROWS * CDIM];           // x after attention residual
__device__ float g_fc1[ROWS * HID];           // gelu(fc1) output

// ---------------- LayerNorm: one block per row of 768 ----------------
__global__ void ln_kernel(const float* __restrict__ x, const float* __restrict__ gam,
                          const float* __restrict__ bet, float* __restrict__ out) {
    __shared__ float red[8];
    const int t = threadIdx.x;
    const float* xr = x + (size_t)blockIdx.x * CDIM;
    float* orow = out + (size_t)blockIdx.x * CDIM;

    float v0 = xr[t], v1 = xr[t + 256], v2 = xr[t + 512];

    float s = v0 + v1 + v2;
#pragma unroll
    for (int o = 16; o; o >>= 1) s += __shfl_xor_sync(~0u, s, o);
    if ((t & 31) == 0) red[t >> 5] = s;
    __syncthreads();
    s = red[0] + red[1] + red[2] + red[3] + red[4] + red[5] + red[6] + red[7];
    const float mu = s * (1.0f / CDIM);
    __syncthreads();

    float d0 = v0 - mu, d1 = v1 - mu, d2 = v2 - mu;
    float q = d0 * d0 + d1 * d1 + d2 * d2;
#pragma unroll
    for (int o = 16; o; o >>= 1) q += __shfl_xor_sync(~0u, q, o);
    if ((t & 31) == 0) red[t >> 5] = q;
    __syncthreads();
    q = red[0] + red[1] + red[2] + red[3] + red[4] + red[5] + red[6] + red[7];
    const float rs = rsqrtf(q * (1.0f / CDIM) + 1e-5f);

    orow[t]       = d0 * rs * gam[t]       + bet[t];
    orow[t + 256] = d1 * rs * gam[t + 256] + bet[t + 256];
    orow[t + 512] = d2 * rs * gam[t + 512] + bet[t + 512];
}

// ---------------- Softmax over rows of 2048 (scale folded in) ----------------
__global__ void softmax_kernel(float* __restrict__ S) {
    __shared__ float red[8];
    float* p = S + (size_t)blockIdx.x * SEQ;
    const int t = threadIdx.x;
    float v[8];
#pragma unroll
    for (int i = 0; i < 8; i++) v[i] = p[t + (i << 8)] * 0.125f;  // *= head_dim^-0.5

    float m = v[0];
#pragma unroll
    for (int i = 1; i < 8; i++) m = fmaxf(m, v[i]);
#pragma unroll
    for (int o = 16; o; o >>= 1) m = fmaxf(m, __shfl_xor_sync(~0u, m, o));
    if ((t & 31) == 0) red[t >> 5] = m;
    __syncthreads();
    m = fmaxf(fmaxf(fmaxf(red[0], red[1]), fmaxf(red[2], red[3])),
              fmaxf(fmaxf(red[4], red[5]), fmaxf(red[6], red[7])));
    __syncthreads();

    float s = 0.f;
#pragma unroll
    for (int i = 0; i < 8; i++) { v[i] = expf(v[i] - m); s += v[i]; }
#pragma unroll
    for (int o = 16; o; o >>= 1) s += __shfl_xor_sync(~0u, s, o);
    if ((t & 31) == 0) red[t >> 5] = s;
    __syncthreads();
    s = red[0] + red[1] + red[2] + red[3] + red[4] + red[5] + red[6] + red[7];
    const float inv = 1.0f / s;
#pragma unroll
    for (int i = 0; i < 8; i++) p[t + (i << 8)] = v[i] * inv;
}

// ---------------- Generic NT SGEMM: C[M,N] = A[M,K] * B[N,K]^T (+epilogue) ----------------
// 128x128 tile, BK=16, 256 threads, 8x8 micro-tile. All dims are multiples of
// the tile sizes for every call site, so no bounds checks.
// EPI: 0=none, 1=+bias, 2=+bias+residual, 3=gelu(+bias)
// Batched z support: per z, offset = (z/hz)*s?b + (z%hz)*s?h  (hz=1 => no-op)
template <int EPI>
__launch_bounds__(256, 2)
__global__ void gemm_nt(const float* __restrict__ A, int lda,
                        const float* __restrict__ B, int ldb,
                        float* __restrict__ C, int ldc, int K,
                        const float* __restrict__ bias,
                        const float* __restrict__ res,
                        int hz, size_t sAb, size_t sAh, size_t sBb, size_t sBh,
                        size_t sCb, size_t sCh) {
    __shared__ float As[16][128];
    __shared__ float Bs[16][128];

    const int z = blockIdx.z;
    A += (size_t)(z / hz) * sAb + (size_t)(z % hz) * sAh;
    B += (size_t)(z / hz) * sBb + (size_t)(z % hz) * sBh;
    C += (size_t)(z / hz) * sCb + (size_t)(z % hz) * sCh;

    const int m0 = blockIdx.y * 128;
    const int n0 = blockIdx.x * 128;
    const int t = threadIdx.x;

    const int lr = t >> 2;          // 0..63
    const int lc = (t & 3) << 2;    // 0,4,8,12
    const float* Ag = A + (size_t)(m0 + lr) * lda + lc;
    const float* Bg = B + (size_t)(n0 + lr) * ldb + lc;

    const int tm = (t >> 4) << 3;   // row offset of 8-row micro tile
    const int tn = (t & 15) << 3;   // col offset of 8-col micro tile

    float acc[8][8] = {};

    for (int k0 = 0; k0 < K; k0 += 16) {
        float4 a0 = *(const float4*)Ag;
        float4 a1 = *(const float4*)(Ag + (size_t)64 * lda);
        float4 b0 = *(const float4*)Bg;
        float4 b1 = *(const float4*)(Bg + (size_t)64 * ldb);
        Ag += 16; Bg += 16;

        As[lc + 0][lr] = a0.x; As[lc + 1][lr] = a0.y; As[lc + 2][lr] = a0.z; As[lc + 3][lr] = a0.w;
        As[lc + 0][lr + 64] = a1.x; As[lc + 1][lr + 64] = a1.y; As[lc + 2][lr + 64] = a1.z; As[lc + 3][lr + 64] = a1.w;
        Bs[lc + 0][lr] = b0.x; Bs[lc + 1][lr] = b0.y; Bs[lc + 2][lr] = b0.z; Bs[lc + 3][lr] = b0.w;
        Bs[lc + 0][lr + 64] = b1.x; Bs[lc + 1][lr + 64] = b1.y; Bs[lc + 2][lr + 64] = b1.z; Bs[lc + 3][lr + 64] = b1.w;
        __syncthreads();

#pragma unroll
        for (int k = 0; k < 16; k++) {
            float4 af0 = *(const float4*)&As[k][tm];
            float4 af1 = *(const float4*)&As[k][tm + 4];
            float4 bf0 = *(const float4*)&Bs[k][tn];
            float4 bf1 = *(const float4*)&Bs[k][tn + 4];
            float a_[8] = {af0.x, af0.y, af0.z, af0.w, af1.x, af1.y, af1.z, af1.w};
            float b_[8] = {bf0.x, bf0.y, bf0.z, bf0.w, bf1.x, bf1.y, bf1.z, bf1.w};
#pragma unroll
            for (int i = 0; i < 8; i++)
#pragma unroll
                for (int j = 0; j < 8; j++)
                    acc[i][j] = fmaf(a_[i], b_[j], acc[i][j]);
        }
        __syncthreads();
    }

    float bb[8];
    if (EPI != 0) {
#pragma unroll
        for (int j = 0; j < 8; j++) bb[j] = bias[n0 + tn + j];
    }

#pragma unroll
    for (int i = 0; i < 8; i++) {
        const int m = m0 + tm + i;
        float* cp = C + (size_t)m * ldc + n0 + tn;
        const float* rp = (EPI == 2) ? (res + (size_t)m * ldc + n0 + tn) : nullptr;
#pragma unroll
        for (int j = 0; j < 8; j++) {
            float v = acc[i][j];
            if (EPI != 0) v += bb[j];
            if (EPI == 2) v += rp[j];
            if (EPI == 3) v = 0.5f * v * (1.0f + erff(v * 0.70710678118654752f));
            cp[j] = v;
        }
    }
}

// ---------------- PV GEMM: O[z][m,d] = sum_n P[m,n] * V[n,d]  (NN flavor) ----------------
// Per z=(b*12+h): A = S[z] (lda=2048), B = V slice of qkv (ldb=2304, d contiguous),
// C = attn[(b,n),h*64+d] (ldc=768). M=2048, N=64(full), K=2048.
__launch_bounds__(256, 2)
__global__ void gemm_pv(const float* __restrict__ S, const float* __restrict__ qkv,
                        float* __restrict__ O) {
    __shared__ float As[16][128];
    __shared__ float Bs[16][64];

    const int z = blockIdx.y;
    const int b = z / NHEAD, h = z % NHEAD;
    const float* A = S + (size_t)z * SEQ * SEQ;
    const float* B = qkv + (size_t)b * SEQ * QKVDIM + 2 * CDIM + h * HDIM;
    float* C = O + (size_t)b * SEQ * CDIM + h * HDIM;

    const int m0 = blockIdx.x * 128;
    const int t = threadIdx.x;

    const int lr = t >> 2;
    const int lc = (t & 3) << 2;
    const float* Ag = A + (size_t)(m0 + lr) * SEQ + lc;
    const float* Bg = B + (size_t)(t >> 4) * QKVDIM + ((t & 15) << 2);

    const int tm = (t >> 4) << 3;   // 8 rows
    const int tn = (t & 15) << 2;   // 4 cols

    float acc[8][4] = {};

    for (int k0 = 0; k0 < SEQ; k0 += 16) {
        float4 a0 = *(const float4*)Ag;
        float4 a1 = *(const float4*)(Ag + (size_t)64 * SEQ);
        float4 b0 = *(const float4*)Bg;
        Ag += 16; Bg += (size_t)16 * QKVDIM;

        As[lc + 0][lr] = a0.x; As[lc + 1][lr] = a0.y; As[lc + 2][lr] = a0.z; As[lc + 3][lr] = a0.w;
        As[lc + 0][lr + 64] = a1.x; As[lc + 1][lr + 64] = a1.y; As[lc + 2][lr + 64] = a1.z; As[lc + 3][lr + 64] = a1.w;
        *(float4*)&Bs[t >> 4][(t & 15) << 2] = b0;
        __syncthreads();

#pragma unroll
        for (int k = 0; k < 16; k++) {
            float4 af0 = *(const float4*)&As[k][tm];
            float4 af1 = *(const float4*)&As[k][tm + 4];
            float4 bf = *(const float4*)&Bs[k][tn];
            float a_[8] = {af0.x, af0.y, af0.z, af0.w, af1.x, af1.y, af1.z, af1.w};
            float b_[4] = {bf.x, bf.y, bf.z, bf.w};
#pragma unroll
            for (int i = 0; i < 8; i++)
#pragma unroll
                for (int j = 0; j < 4; j++)
                    acc[i][j] = fmaf(a_[i], b_[j], acc[i][j]);
        }
        __syncthreads();
    }

#pragma unroll
    for (int i = 0; i < 8; i++) {
        float4 v = make_float4(acc[i][0], acc[i][1], acc[i][2], acc[i][3]);
        *(float4*)(C + (size_t)(m0 + tm + i) * CDIM + tn) = v;
    }
}

// ---------------- launch ----------------
extern "C" void kernel_launch(void* const* d_in, const int* in_sizes, int n_in,
                              void* d_out, int out_size) {
    const float* x      = (const float*)d_in[0];
    const float* ln1_g  = (const float*)d_in[1];
    const float* ln1_b  = (const float*)d_in[2];
    const float* qkv_w  = (const float*)d_in[3];
    const float* proj_w = (const float*)d_in[4];
    const float* proj_b = (const float*)d_in[5];
    const float* ln2_g  = (const float*)d_in[6];
    const float* ln2_b  = (const float*)d_in[7];
    const float* fc1_w  = (const float*)d_in[8];
    const float* fc1_b  = (const float*)d_in[9];
    const float* fc2_w  = (const float*)d_in[10];
    const float* fc2_b  = (const float*)d_in[11];
    float* out = (float*)d_out;

    float *h, *qkv, *S, *attn, *x1, *fc1;
    cudaGetSymbolAddress((void**)&h, g_h);
    cudaGetSymbolAddress((void**)&qkv, g_qkv);
    cudaGetSymbolAddress((void**)&S, g_S);
    cudaGetSymbolAddress((void**)&attn, g_attn);
    cudaGetSymbolAddress((void**)&x1, g_x1);
    cudaGetSymbolAddress((void**)&fc1, g_fc1);

    // 1) LN1
    ln_kernel<<<ROWS, 256>>>(x, ln1_g, ln1_b, h);

    // 2) QKV: [4096,768] x [2304,768]^T -> [4096,2304]
    gemm_nt<0><<<dim3(QKVDIM / 128, ROWS / 128, 1), 256>>>(
        h, CDIM, qkv_w, CDIM, qkv, QKVDIM, CDIM,
        nullptr, nullptr, 1, 0, 0, 0, 0, 0, 0);

    // 3) S = Q K^T per (b,h): M=N=2048, K=64, z=24
    gemm_nt<0><<<dim3(SEQ / 128, SEQ / 128, 24), 256>>>(
        qkv, QKVDIM, qkv + CDIM, QKVDIM, S, SEQ, HDIM,
        nullptr, nullptr, NHEAD,
        (size_t)SEQ * QKVDIM, (size_t)HDIM,
        (size_t)SEQ * QKVDIM, (size_t)HDIM,
        (size_t)NHEAD * SEQ * SEQ, (size_t)SEQ * SEQ);

    // 4) softmax rows (scale folded in)
    softmax_kernel<<<24 * SEQ, 256>>>(S);

    // 5) O = P V  -> attn [4096, 768]
    gemm_pv<<<dim3(SEQ / 128, 24), 256>>>(S, qkv, attn);

    // 6) x1 = x + attn @ proj_w^T + proj_b
    gemm_nt<2><<<dim3(CDIM / 128, ROWS / 128, 1), 256>>>(
        attn, CDIM, proj_w, CDIM, x1, CDIM, CDIM,
        proj_b, x, 1, 0, 0, 0, 0, 0, 0);

    // 7) LN2
    ln_kernel<<<ROWS, 256>>>(x1, ln2_g, ln2_b, h);

    // 8) fc1 + exact GELU -> [4096, 3072]
    gemm_nt<3><<<dim3(HID / 128, ROWS / 128, 1), 256>>>(
        h, CDIM, fc1_w, CDIM, fc1, HID, CDIM,
        fc1_b, nullptr, 1, 0, 0, 0, 0, 0, 0);

    // 9) out = x1 + fc1 @ fc2_w^T + fc2_b
    gemm_nt<2><<<dim3(CDIM / 128, ROWS / 128, 1), 256>>>(
        fc1, HID, fc2_w, HID, out, CDIM, HID,
        fc2_b, x1, 1, 0, 0, 0, 0, 0, 0);
}

// round 2
// speedup vs baseline: 1.9970x; 1.9970x over previous
#include <cuda_runtime.h>
#include <math.h>
#include <stdint.h>

// x: [2, 2048, 768]; heads=12, head_dim=64, mlp=3072
#define ROWS   4096
#define CDIM   768
#define QKVDIM 2304
#define HID    3072
#define NHEAD  12
#define HDIM   64
#define SEQ    2048

// ---------------- scratch ----------------
__device__ float g_h[ROWS * CDIM];
__device__ float g_qkv[ROWS * QKVDIM];
__device__ float g_S[(long long)24 * SEQ * SEQ];
__device__ float g_attn[ROWS * CDIM];
__device__ float g_x1[ROWS * CDIM];
__device__ float g_fc1[ROWS * HID];
__device__ float g_vt[24 * HDIM * SEQ];   // transposed V: [z][d][seq]

// ---------------- LayerNorm ----------------
__global__ void ln_kernel(const float* __restrict__ x, const float* __restrict__ gam,
                          const float* __restrict__ bet, float* __restrict__ out) {
    __shared__ float red[8];
    const int t = threadIdx.x;
    const float* xr = x + (size_t)blockIdx.x * CDIM;
    float* orow = out + (size_t)blockIdx.x * CDIM;

    float v0 = xr[t], v1 = xr[t + 256], v2 = xr[t + 512];

    float s = v0 + v1 + v2;
#pragma unroll
    for (int o = 16; o; o >>= 1) s += __shfl_xor_sync(~0u, s, o);
    if ((t & 31) == 0) red[t >> 5] = s;
    __syncthreads();
    s = red[0] + red[1] + red[2] + red[3] + red[4] + red[5] + red[6] + red[7];
    const float mu = s * (1.0f / CDIM);
    __syncthreads();

    float d0 = v0 - mu, d1 = v1 - mu, d2 = v2 - mu;
    float q = d0 * d0 + d1 * d1 + d2 * d2;
#pragma unroll
    for (int o = 16; o; o >>= 1) q += __shfl_xor_sync(~0u, q, o);
    if ((t & 31) == 0) red[t >> 5] = q;
    __syncthreads();
    q = red[0] + red[1] + red[2] + red[3] + red[4] + red[5] + red[6] + red[7];
    const float rs = rsqrtf(q * (1.0f / CDIM) + 1e-5f);

    orow[t]       = d0 * rs * gam[t]       + bet[t];
    orow[t + 256] = d1 * rs * gam[t + 256] + bet[t + 256];
    orow[t + 512] = d2 * rs * gam[t + 512] + bet[t + 512];
}

// ---------------- Softmax (scale folded) ----------------
__global__ void softmax_kernel(float* __restrict__ S) {
    __shared__ float red[8];
    float* p = S + (size_t)blockIdx.x * SEQ;
    const int t = threadIdx.x;
    float v[8];
#pragma unroll
    for (int i = 0; i < 8; i++) v[i] = p[t + (i << 8)] * 0.125f;

    float m = v[0];
#pragma unroll
    for (int i = 1; i < 8; i++) m = fmaxf(m, v[i]);
#pragma unroll
    for (int o = 16; o; o >>= 1) m = fmaxf(m, __shfl_xor_sync(~0u, m, o));
    if ((t & 31) == 0) red[t >> 5] = m;
    __syncthreads();
    m = fmaxf(fmaxf(fmaxf(red[0], red[1]), fmaxf(red[2], red[3])),
              fmaxf(fmaxf(red[4], red[5]), fmaxf(red[6], red[7])));
    __syncthreads();

    float s = 0.f;
#pragma unroll
    for (int i = 0; i < 8; i++) { v[i] = expf(v[i] - m); s += v[i]; }
#pragma unroll
    for (int o = 16; o; o >>= 1) s += __shfl_xor_sync(~0u, s, o);
    if ((t & 31) == 0) red[t >> 5] = s;
    __syncthreads();
    s = red[0] + red[1] + red[2] + red[3] + red[4] + red[5] + red[6] + red[7];
    const float inv = 1.0f / s;
#pragma unroll
    for (int i = 0; i < 8; i++) p[t + (i << 8)] = v[i] * inv;
}

// ---------------- V transpose: vt[z][d][seq] = qkv[b, seq, 2C + h*64 + d] ----------------
__global__ void transpose_v(const float* __restrict__ qkv, float* __restrict__ vt) {
    __shared__ float tile[32][33];
    const int z = blockIdx.z, b = z / NHEAD, h = z % NHEAD;
    const float* V = qkv + (size_t)b * SEQ * QKVDIM + 2 * CDIM + h * HDIM;
    float* O = vt + (size_t)z * HDIM * SEQ;
    const int k0 = blockIdx.x << 5, n0 = blockIdx.y << 5;
    const int tx = threadIdx.x, ty = threadIdx.y;
#pragma unroll
    for (int i = 0; i < 32; i += 8)
        tile[ty + i][tx] = V[(size_t)(k0 + ty + i) * QKVDIM + n0 + tx];
    __syncthreads();
#pragma unroll
    for (int i = 0; i < 32; i += 8)
        O[(size_t)(n0 + ty + i) * SEQ + k0 + tx] = tile[tx][ty + i];
}

// ---------------- TF32 tensor-core NT GEMM ----------------
__device__ __forceinline__ uint32_t f2tf32(float v) {
    uint32_t u; asm("cvt.rna.tf32.f32 %0, %1;" : "=r"(u) : "f"(v)); return u;
}

__device__ __forceinline__ void mma8(float* c, const uint4 a, const uint2 b) {
    asm volatile(
        "mma.sync.aligned.m16n8k8.row.col.f32.tf32.tf32.f32 "
        "{%0,%1,%2,%3}, {%4,%5,%6,%7}, {%8,%9}, {%0,%1,%2,%3};"
        : "+f"(c[0]), "+f"(c[1]), "+f"(c[2]), "+f"(c[3])
        : "r"(a.x), "r"(a.y), "r"(a.z), "r"(a.w), "r"(b.x), "r"(b.y));
}

// C[M,N] = A[M,K] @ B[N,K]^T, all row-major, dims multiples of tile sizes.
// EPI: 0=none, 2=+bias+res, 3=gelu(+bias)
template <int EPI, int WARP_M, int WARP_N, int WM_T, int WN_T>
__launch_bounds__(WARP_M* WARP_N * 32)
__global__ void gemm_tc(const float* __restrict__ A, int lda,
                        const float* __restrict__ B, int ldb,
                        float* __restrict__ C, int ldc, int K,
                        const float* __restrict__ bias,
                        const float* __restrict__ res,
                        int hz, size_t sAb, size_t sAh, size_t sBb, size_t sBh,
                        size_t sCb, size_t sCh) {
    constexpr int NW = WARP_M * WARP_N;
    constexpr int BM = WARP_M * WM_T * 16;
    constexpr int BN = WARP_N * WN_T * 8;
    constexpr int NFA = (BM / 16) * 2 / NW;   // A fragments staged per warp per BK
    constexpr int NFB = (BN / 8) * 2 / NW;

    __shared__ uint32_t sA[2][BM * 16];
    __shared__ uint32_t sB[2][BN * 16];

    const int z = blockIdx.z;
    A += (size_t)(z / hz) * sAb + (size_t)(z % hz) * sAh;
    B += (size_t)(z / hz) * sBb + (size_t)(z % hz) * sBh;
    C += (size_t)(z / hz) * sCb + (size_t)(z % hz) * sCh;

    const int m0 = blockIdx.y * BM;
    const int n0 = blockIdx.x * BN;
    const int t = threadIdx.x;
    const int lane = t & 31, warp = t >> 5;
    const int wm = warp / WARP_N, wn = warp % WARP_N;
    const int lr = lane >> 2, lc = lane & 3;

    float ra[NFA][4], rb[NFB][2];

    // global -> regs (fragment-shaped scalar loads)
    auto loadG = [&](int kk) {
#pragma unroll
        for (int i = 0; i < NFA; i++) {
            const int f = warp * NFA + i, mt = f >> 1, ks = f & 1;
            const float* p = A + (size_t)(m0 + mt * 16 + lr) * lda + kk + ks * 8 + lc;
            ra[i][0] = p[0];
            ra[i][1] = p[8 * lda];
            ra[i][2] = p[4];
            ra[i][3] = p[8 * lda + 4];
        }
#pragma unroll
        for (int i = 0; i < NFB; i++) {
            const int f = warp * NFB + i, nt = f >> 1, ks = f & 1;
            const float* p = B + (size_t)(n0 + nt * 8 + lr) * ldb + kk + ks * 8 + lc;
            rb[i][0] = p[0];
            rb[i][1] = p[4];
        }
    };
    // regs -> smem (tf32 convert, conflict-free wide stores)
    auto stage = [&](int bb) {
#pragma unroll
        for (int i = 0; i < NFA; i++) {
            const int f = warp * NFA + i;
            uint4 v = make_uint4(f2tf32(ra[i][0]), f2tf32(ra[i][1]),
                                 f2tf32(ra[i][2]), f2tf32(ra[i][3]));
            ((uint4*)sA[bb])[f * 32 + lane] = v;
        }
#pragma unroll
        for (int i = 0; i < NFB; i++) {
            const int f = warp * NFB + i;
            uint2 v = make_uint2(f2tf32(rb[i][0]), f2tf32(rb[i][1]));
            ((uint2*)sB[bb])[f * 32 + lane] = v;
        }
    };

    float acc[WM_T][WN_T][4] = {};

    loadG(0);
    stage(0);
    __syncthreads();

    int buf = 0;
    for (int k0 = 0; k0 < K; k0 += 16) {
        const bool nxt = (k0 + 16) < K;
        if (nxt) loadG(k0 + 16);

#pragma unroll
        for (int ks = 0; ks < 2; ks++) {
            uint4 af[WM_T];
            uint2 bf[WN_T];
#pragma unroll
            for (int mi = 0; mi < WM_T; mi++)
                af[mi] = ((const uint4*)sA[buf])[(((wm * WM_T + mi) << 1) + ks) * 32 + lane];
#pragma unroll
            for (int ni = 0; ni < WN_T; ni++)
                bf[ni] = ((const uint2*)sB[buf])[(((wn * WN_T + ni) << 1) + ks) * 32 + lane];
#pragma unroll
            for (int mi = 0; mi < WM_T; mi++)
#pragma unroll
                for (int ni = 0; ni < WN_T; ni++)
                    mma8(acc[mi][ni], af[mi], bf[ni]);
        }
        __syncthreads();
        if (nxt) {
            stage(buf ^ 1);
            buf ^= 1;
            __syncthreads();
        }
    }

    // epilogue
#pragma unroll
    for (int mi = 0; mi < WM_T; mi++) {
        const int m = m0 + (wm * WM_T + mi) * 16 + lr;
#pragma unroll
        for (int ni = 0; ni < WN_T; ni++) {
            const int n = n0 + (wn * WN_T + ni) * 8 + (lc << 1);
            float2 bb = make_float2(0.f, 0.f);
            if (EPI != 0) bb = *(const float2*)(bias + n);
#pragma unroll
            for (int half = 0; half < 2; half++) {
                const int mm = m + half * 8;
                float v0 = acc[mi][ni][half * 2 + 0];
                float v1 = acc[mi][ni][half * 2 + 1];
                if (EPI != 0) { v0 += bb.x; v1 += bb.y; }
                if (EPI == 2) {
                    float2 r2 = *(const float2*)(res + (size_t)mm * ldc + n);
                    v0 += r2.x; v1 += r2.y;
                }
                if (EPI == 3) {
                    v0 = 0.5f * v0 * (1.0f + erff(v0 * 0.70710678118654752f));
                    v1 = 0.5f * v1 * (1.0f + erff(v1 * 0.70710678118654752f));
                }
                *(float2*)(C + (size_t)mm * ldc + n) = make_float2(v0, v1);
            }
        }
    }
}

// ---------------- launch ----------------
extern "C" void kernel_launch(void* const* d_in, const int* in_sizes, int n_in,
                              void* d_out, int out_size) {
    const float* x      = (const float*)d_in[0];
    const float* ln1_g  = (const float*)d_in[1];
    const float* ln1_b  = (const float*)d_in[2];
    const float* qkv_w  = (const float*)d_in[3];
    const float* proj_w = (const float*)d_in[4];
    const float* proj_b = (const float*)d_in[5];
    const float* ln2_g  = (const float*)d_in[6];
    const float* ln2_b  = (const float*)d_in[7];
    const float* fc1_w  = (const float*)d_in[8];
    const float* fc1_b  = (const float*)d_in[9];
    const float* fc2_w  = (const float*)d_in[10];
    const float* fc2_b  = (const float*)d_in[11];
    float* out = (float*)d_out;

    float *h, *qkv, *S, *attn, *x1, *fc1, *vt;
    cudaGetSymbolAddress((void**)&h, g_h);
    cudaGetSymbolAddress((void**)&qkv, g_qkv);
    cudaGetSymbolAddress((void**)&S, g_S);
    cudaGetSymbolAddress((void**)&attn, g_attn);
    cudaGetSymbolAddress((void**)&x1, g_x1);
    cudaGetSymbolAddress((void**)&fc1, g_fc1);
    cudaGetSymbolAddress((void**)&vt, g_vt);

    // 1) LN1
    ln_kernel<<<ROWS, 256>>>(x, ln1_g, ln1_b, h);

    // 2) QKV: [4096,768] x [2304,768]^T
    gemm_tc<0, 2, 4, 4, 4><<<dim3(QKVDIM / 128, ROWS / 128, 1), 256>>>(
        h, CDIM, qkv_w, CDIM, qkv, QKVDIM, CDIM,
        nullptr, nullptr, 1, 0, 0, 0, 0, 0, 0);

    // 3) S = Q K^T per (b,h)
    gemm_tc<0, 2, 4, 4, 4><<<dim3(SEQ / 128, SEQ / 128, 24), 256>>>(
        qkv, QKVDIM, qkv + CDIM, QKVDIM, S, SEQ, HDIM,
        nullptr, nullptr, NHEAD,
        (size_t)SEQ * QKVDIM, (size_t)HDIM,
        (size_t)SEQ * QKVDIM, (size_t)HDIM,
        (size_t)NHEAD * SEQ * SEQ, (size_t)SEQ * SEQ);

    // 4) softmax
    softmax_kernel<<<24 * SEQ, 256>>>(S);

    // 5) transpose V, then O = P @ Vt^T
    transpose_v<<<dim3(SEQ / 32, HDIM / 32, 24), dim3(32, 8)>>>(qkv, vt);
    gemm_tc<0, 4, 2, 2, 4><<<dim3(HDIM / 64, SEQ / 128, 24), 256>>>(
        S, SEQ, vt, SEQ, attn, CDIM, SEQ,
        nullptr, nullptr, NHEAD,
        (size_t)NHEAD * SEQ * SEQ, (size_t)SEQ * SEQ,
        (size_t)NHEAD * HDIM * SEQ, (size_t)HDIM * SEQ,
        (size_t)SEQ * CDIM, (size_t)HDIM);

    // 6) x1 = x + attn @ proj_w^T + proj_b
    gemm_tc<2, 2, 4, 4, 4><<<dim3(CDIM / 128, ROWS / 128, 1), 256>>>(
        attn, CDIM, proj_w, CDIM, x1, CDIM, CDIM,
        proj_b, x, 1, 0, 0, 0, 0, 0, 0);

    // 7) LN2
    ln_kernel<<<ROWS, 256>>>(x1, ln2_g, ln2_b, h);

    // 8) fc1 + exact GELU
    gemm_tc<3, 2, 4, 4, 4><<<dim3(HID / 128, ROWS / 128, 1), 256>>>(
        h, CDIM, fc1_w, CDIM, fc1, HID, CDIM,
        fc1_b, nullptr, 1, 0, 0, 0, 0, 0, 0);

    // 9) out = x1 + fc1 @ fc2_w^T + fc2_b
    gemm_tc<2, 2, 4, 4, 4><<<dim3(CDIM / 128, ROWS / 128, 1), 256>>>(
        fc1, HID, fc2_w, HID, out, CDIM, HID,
        fc2_b, x1, 1, 0, 0, 0, 0, 0, 0);
}

// round 3
// speedup vs baseline: 3.3757x; 1.6904x over previous
#include <cuda_runtime.h>
#include <math.h>
#include <stdint.h>

// x: [2, 2048, 768]; heads=12, head_dim=64, mlp=3072
#define ROWS   4096
#define CDIM   768
#define QKVDIM 2304
#define HID    3072
#define NHEAD  12
#define HDIM   64
#define SEQ    2048

// ---------------- scratch ----------------
__device__ float g_h[ROWS * CDIM];
__device__ float g_qkv[ROWS * QKVDIM];
__device__ float g_S[(long long)24 * SEQ * SEQ];
__device__ float g_attn[ROWS * CDIM];
__device__ float g_x1[ROWS * CDIM];
__device__ float g_fc1[ROWS * HID];
__device__ float g_vt[24 * HDIM * SEQ];   // transposed V: [z][d][seq]

// ---------------- LayerNorm ----------------
__global__ void ln_kernel(const float* __restrict__ x, const float* __restrict__ gam,
                          const float* __restrict__ bet, float* __restrict__ out) {
    __shared__ float red[8];
    const int t = threadIdx.x;
    const float* xr = x + (size_t)blockIdx.x * CDIM;
    float* orow = out + (size_t)blockIdx.x * CDIM;

    float v0 = xr[t], v1 = xr[t + 256], v2 = xr[t + 512];

    float s = v0 + v1 + v2;
#pragma unroll
    for (int o = 16; o; o >>= 1) s += __shfl_xor_sync(~0u, s, o);
    if ((t & 31) == 0) red[t >> 5] = s;
    __syncthreads();
    s = red[0] + red[1] + red[2] + red[3] + red[4] + red[5] + red[6] + red[7];
    const float mu = s * (1.0f / CDIM);
    __syncthreads();

    float d0 = v0 - mu, d1 = v1 - mu, d2 = v2 - mu;
    float q = d0 * d0 + d1 * d1 + d2 * d2;
#pragma unroll
    for (int o = 16; o; o >>= 1) q += __shfl_xor_sync(~0u, q, o);
    if ((t & 31) == 0) red[t >> 5] = q;
    __syncthreads();
    q = red[0] + red[1] + red[2] + red[3] + red[4] + red[5] + red[6] + red[7];
    const float rs = rsqrtf(q * (1.0f / CDIM) + 1e-5f);

    orow[t]       = d0 * rs * gam[t]       + bet[t];
    orow[t + 256] = d1 * rs * gam[t + 256] + bet[t + 256];
    orow[t + 512] = d2 * rs * gam[t + 512] + bet[t + 512];
}

// ---------------- Softmax (scale folded) ----------------
__global__ void softmax_kernel(float* __restrict__ S) {
    __shared__ float red[8];
    float* p = S + (size_t)blockIdx.x * SEQ;
    const int t = threadIdx.x;
    float v[8];
#pragma unroll
    for (int i = 0; i < 8; i++) v[i] = p[t + (i << 8)] * 0.125f;

    float m = v[0];
#pragma unroll
    for (int i = 1; i < 8; i++) m = fmaxf(m, v[i]);
#pragma unroll
    for (int o = 16; o; o >>= 1) m = fmaxf(m, __shfl_xor_sync(~0u, m, o));
    if ((t & 31) == 0) red[t >> 5] = m;
    __syncthreads();
    m = fmaxf(fmaxf(fmaxf(red[0], red[1]), fmaxf(red[2], red[3])),
              fmaxf(fmaxf(red[4], red[5]), fmaxf(red[6], red[7])));
    __syncthreads();

    float s = 0.f;
#pragma unroll
    for (int i = 0; i < 8; i++) { v[i] = expf(v[i] - m); s += v[i]; }
#pragma unroll
    for (int o = 16; o; o >>= 1) s += __shfl_xor_sync(~0u, s, o);
    if ((t & 31) == 0) red[t >> 5] = s;
    __syncthreads();
    s = red[0] + red[1] + red[2] + red[3] + red[4] + red[5] + red[6] + red[7];
    const float inv = 1.0f / s;
#pragma unroll
    for (int i = 0; i < 8; i++) p[t + (i << 8)] = v[i] * inv;
}

// ---------------- V transpose ----------------
__global__ void transpose_v(const float* __restrict__ qkv, float* __restrict__ vt) {
    __shared__ float tile[32][33];
    const int z = blockIdx.z, b = z / NHEAD, h = z % NHEAD;
    const float* V = qkv + (size_t)b * SEQ * QKVDIM + 2 * CDIM + h * HDIM;
    float* O = vt + (size_t)z * HDIM * SEQ;
    const int k0 = blockIdx.x << 5, n0 = blockIdx.y << 5;
    const int tx = threadIdx.x, ty = threadIdx.y;
#pragma unroll
    for (int i = 0; i < 32; i += 8)
        tile[ty + i][tx] = V[(size_t)(k0 + ty + i) * QKVDIM + n0 + tx];
    __syncthreads();
#pragma unroll
    for (int i = 0; i < 32; i += 8)
        O[(size_t)(n0 + ty + i) * SEQ + k0 + tx] = tile[tx][ty + i];
}

// ---------------- TF32 tensor-core NT GEMM, cp.async pipeline ----------------
__device__ __forceinline__ void cp16(uint32_t dst, const void* src) {
    asm volatile("cp.async.cg.shared.global [%0], [%1], 16;\n" :: "r"(dst), "l"(src));
}
__device__ __forceinline__ void cp_commit() {
    asm volatile("cp.async.commit_group;\n");
}
__device__ __forceinline__ void cp_wait1() {
    asm volatile("cp.async.wait_group 1;\n");
}

__device__ __forceinline__ void mma8(float* c, const uint32_t* a, const uint32_t* b) {
    asm volatile(
        "mma.sync.aligned.m16n8k8.row.col.f32.tf32.tf32.f32 "
        "{%0,%1,%2,%3}, {%4,%5,%6,%7}, {%8,%9}, {%0,%1,%2,%3};"
        : "+f"(c[0]), "+f"(c[1]), "+f"(c[2]), "+f"(c[3])
        : "r"(a[0]), "r"(a[1]), "r"(a[2]), "r"(a[3]), "r"(b[0]), "r"(b[1]));
}

// swizzled float index: row-major [rows][32], 16B word c in 0..7 stored at c^(row&7)
__device__ __forceinline__ int swz(int row, int c) {
    return (row << 5) + (((c ^ (row & 7))) << 2);
}

// C[M,N] = A[M,K] @ B[N,K]^T (+epilogue). K multiple of 64, tiles exact.
// EPI: 0=none, 2=+bias+res, 3=gelu(+bias)
template <int EPI, int WARP_M, int WARP_N, int WM_T, int WN_T>
__global__ void __launch_bounds__(WARP_M * WARP_N * 32, 2)
gemm_tc(const float* __restrict__ A, int lda,
        const float* __restrict__ B, int ldb,
        float* __restrict__ C, int ldc, int K,
        const float* __restrict__ bias,
        const float* __restrict__ res,
        int hz, size_t sAb, size_t sAh, size_t sBb, size_t sBh,
        size_t sCb, size_t sCh) {
    constexpr int NT = WARP_M * WARP_N * 32;
    constexpr int BM = WARP_M * WM_T * 16;
    constexpr int BN = WARP_N * WN_T * 8;
    constexpr int ASZ = BM * 32;           // floats per A stage
    constexpr int BSZ = BN * 32;
    constexpr int STG = ASZ + BSZ;
    constexpr int NA = ASZ / 4 / NT;       // float4 per thread (A)
    constexpr int NB = BSZ / 4 / NT;

    extern __shared__ uint32_t smem[];
    const uint32_t smem_b = (uint32_t)__cvta_generic_to_shared(smem);

    const int z = blockIdx.z;
    A += (size_t)(z / hz) * sAb + (size_t)(z % hz) * sAh;
    B += (size_t)(z / hz) * sBb + (size_t)(z % hz) * sBh;
    C += (size_t)(z / hz) * sCb + (size_t)(z % hz) * sCh;

    const int m0 = blockIdx.y * BM;
    const int n0 = blockIdx.x * BN;
    const int t = threadIdx.x;
    const int lane = t & 31, warp = t >> 5;
    const int wm = warp / WARP_N, wn = warp % WARP_N;
    const int lr = lane >> 2, lc = lane & 3;

    const float* Abase = A + (size_t)m0 * lda;
    const float* Bbase = B + (size_t)n0 * ldb;

    auto issue = [&](int j, int buf) {
        const float* Ak = Abase + j * 32;
        const uint32_t sa = smem_b + (uint32_t)(buf * STG) * 4u;
#pragma unroll
        for (int i = 0; i < NA; i++) {
            const int idx = t + i * NT;
            const int row = idx >> 3, c = idx & 7;
            cp16(sa + (uint32_t)swz(row, c) * 4u, Ak + (size_t)row * lda + c * 4);
        }
        const float* Bk = Bbase + j * 32;
        const uint32_t sb = smem_b + (uint32_t)(buf * STG + ASZ) * 4u;
#pragma unroll
        for (int i = 0; i < NB; i++) {
            const int idx = t + i * NT;
            const int row = idx >> 3, c = idx & 7;
            cp16(sb + (uint32_t)swz(row, c) * 4u, Bk + (size_t)row * ldb + c * 4);
        }
        cp_commit();
    };

    const int T = K >> 5;   // K/32, always >= 2 here
    issue(0, 0);
    issue(1, 1);

    float acc[WM_T][WN_T][4] = {};
    int buf = 0;

    for (int j = 0; j < T; j++) {
        cp_wait1();
        __syncthreads();
        const uint32_t* a = smem + buf * STG;
        const uint32_t* b = a + ASZ;

#pragma unroll
        for (int ks = 0; ks < 4; ks++) {
            uint32_t af[WM_T][4], bf[WN_T][2];
#pragma unroll
            for (int mt = 0; mt < WM_T; mt++) {
                const int row = (wm * WM_T + mt) * 16 + lr;
                af[mt][0] = a[swz(row,     2 * ks)     + lc];
                af[mt][1] = a[swz(row + 8, 2 * ks)     + lc];
                af[mt][2] = a[swz(row,     2 * ks + 1) + lc];
                af[mt][3] = a[swz(row + 8, 2 * ks + 1) + lc];
            }
#pragma unroll
            for (int nf = 0; nf < WN_T; nf++) {
                const int row = (wn * WN_T + nf) * 8 + lr;
                bf[nf][0] = b[swz(row, 2 * ks)     + lc];
                bf[nf][1] = b[swz(row, 2 * ks + 1) + lc];
            }
#pragma unroll
            for (int mt = 0; mt < WM_T; mt++)
#pragma unroll
                for (int nf = 0; nf < WN_T; nf++)
                    mma8(acc[mt][nf], af[mt], bf[nf]);
        }
        __syncthreads();
        if (j + 2 < T) issue(j + 2, buf);
        else cp_commit();   // keep group count aligned with wait_group 1
        buf ^= 1;
    }

    // epilogue
#pragma unroll
    for (int mi = 0; mi < WM_T; mi++) {
        const int m = m0 + (wm * WM_T + mi) * 16 + lr;
#pragma unroll
        for (int ni = 0; ni < WN_T; ni++) {
            const int n = n0 + (wn * WN_T + ni) * 8 + (lc << 1);
            float2 bb = make_float2(0.f, 0.f);
            if (EPI != 0) bb = *(const float2*)(bias + n);
#pragma unroll
            for (int half = 0; half < 2; half++) {
                const int mm = m + half * 8;
                float v0 = acc[mi][ni][half * 2 + 0];
                float v1 = acc[mi][ni][half * 2 + 1];
                if (EPI != 0) { v0 += bb.x; v1 += bb.y; }
                if (EPI == 2) {
                    float2 r2 = *(const float2*)(res + (size_t)mm * ldc + n);
                    v0 += r2.x; v1 += r2.y;
                }
                if (EPI == 3) {
                    v0 = 0.5f * v0 * (1.0f + erff(v0 * 0.70710678118654752f));
                    v1 = 0.5f * v1 * (1.0f + erff(v1 * 0.70710678118654752f));
                }
                *(float2*)(C + (size_t)mm * ldc + n) = make_float2(v0, v1);
            }
        }
    }
}

// ---------------- launch ----------------
extern "C" void kernel_launch(void* const* d_in, const int* in_sizes, int n_in,
                              void* d_out, int out_size) {
    const float* x      = (const float*)d_in[0];
    const float* ln1_g  = (const float*)d_in[1];
    const float* ln1_b  = (const float*)d_in[2];
    const float* qkv_w  = (const float*)d_in[3];
    const float* proj_w = (const float*)d_in[4];
    const float* proj_b = (const float*)d_in[5];
    const float* ln2_g  = (const float*)d_in[6];
    const float* ln2_b  = (const float*)d_in[7];
    const float* fc1_w  = (const float*)d_in[8];
    const float* fc1_b  = (const float*)d_in[9];
    const float* fc2_w  = (const float*)d_in[10];
    const float* fc2_b  = (const float*)d_in[11];
    float* out = (float*)d_out;

    float *h, *qkv, *S, *attn, *x1, *fc1, *vt;
    cudaGetSymbolAddress((void**)&h, g_h);
    cudaGetSymbolAddress((void**)&qkv, g_qkv);
    cudaGetSymbolAddress((void**)&S, g_S);
    cudaGetSymbolAddress((void**)&attn, g_attn);
    cudaGetSymbolAddress((void**)&x1, g_x1);
    cudaGetSymbolAddress((void**)&fc1, g_fc1);
    cudaGetSymbolAddress((void**)&vt, g_vt);

    constexpr int SM128 = 2 * (128 * 32 + 128 * 32) * 4;  // 64KB
    constexpr int SMPV  = 2 * (128 * 32 + 64 * 32) * 4;   // 48KB
    cudaFuncSetAttribute(gemm_tc<0, 2, 4, 4, 4>, cudaFuncAttributeMaxDynamicSharedMemorySize, SM128);
    cudaFuncSetAttribute(gemm_tc<2, 2, 4, 4, 4>, cudaFuncAttributeMaxDynamicSharedMemorySize, SM128);
    cudaFuncSetAttribute(gemm_tc<3, 2, 4, 4, 4>, cudaFuncAttributeMaxDynamicSharedMemorySize, SM128);
    cudaFuncSetAttribute(gemm_tc<0, 4, 2, 2, 4>, cudaFuncAttributeMaxDynamicSharedMemorySize, SMPV);

    // 1) LN1
    ln_kernel<<<ROWS, 256>>>(x, ln1_g, ln1_b, h);

    // 2) QKV: [4096,768] x [2304,768]^T
    gemm_tc<0, 2, 4, 4, 4><<<dim3(QKVDIM / 128, ROWS / 128, 1), 256, SM128>>>(
        h, CDIM, qkv_w, CDIM, qkv, QKVDIM, CDIM,
        nullptr, nullptr, 1, 0, 0, 0, 0, 0, 0);

    // 3) S = Q K^T per (b,h): K=64
    gemm_tc<0, 2, 4, 4, 4><<<dim3(SEQ / 128, SEQ / 128, 24), 256, SM128>>>(
        qkv, QKVDIM, qkv + CDIM, QKVDIM, S, SEQ, HDIM,
        nullptr, nullptr, NHEAD,
        (size_t)SEQ * QKVDIM, (size_t)HDIM,
        (size_t)SEQ * QKVDIM, (size_t)HDIM,
        (size_t)NHEAD * SEQ * SEQ, (size_t)SEQ * SEQ);

    // 4) softmax
    softmax_kernel<<<24 * SEQ, 256>>>(S);

    // 5) transpose V, then O = P @ Vt^T
    transpose_v<<<dim3(SEQ / 32, HDIM / 32, 24), dim3(32, 8)>>>(qkv, vt);
    gemm_tc<0, 4, 2, 2, 4><<<dim3(HDIM / 64, SEQ / 128, 24), 256, SMPV>>>(
        S, SEQ, vt, SEQ, attn, CDIM, SEQ,
        nullptr, nullptr, NHEAD,
        (size_t)NHEAD * SEQ * SEQ, (size_t)SEQ * SEQ,
        (size_t)NHEAD * HDIM * SEQ, (size_t)HDIM * SEQ,
        (size_t)SEQ * CDIM, (size_t)HDIM);

    // 6) x1 = x + attn @ proj_w^T + proj_b
    gemm_tc<2, 2, 4, 4, 4><<<dim3(CDIM / 128, ROWS / 128, 1), 256, SM128>>>(
        attn, CDIM, proj_w, CDIM, x1, CDIM, CDIM,
        proj_b, x, 1, 0, 0, 0, 0, 0, 0);

    // 7) LN2
    ln_kernel<<<ROWS, 256>>>(x1, ln2_g, ln2_b, h);

    // 8) fc1 + exact GELU
    gemm_tc<3, 2, 4, 4, 4><<<dim3(HID / 128, ROWS / 128, 1), 256, SM128>>>(
        h, CDIM, fc1_w, CDIM, fc1, HID, CDIM,
        fc1_b, nullptr, 1, 0, 0, 0, 0, 0, 0);

    // 9) out = x1 + fc1 @ fc2_w^T + fc2_b
    gemm_tc<2, 2, 4, 4, 4><<<dim3(CDIM / 128, ROWS / 128, 1), 256, SM128>>>(
        fc1, HID, fc2_w, HID, out, CDIM, HID,
        fc2_b, x1, 1, 0, 0, 0, 0, 0, 0);
}

// round 5
// speedup vs baseline: 4.3522x; 1.2893x over previous
#include <cuda_runtime.h>
#include <math.h>
#include <stdint.h>

// x: [2, 2048, 768]; heads=12, head_dim=64, mlp=3072
#define ROWS   4096
#define CDIM   768
#define QKVDIM 2304
#define HID    3072
#define NHEAD  12
#define HDIM   64
#define SEQ    2048

// ---------------- scratch ----------------
__device__ float g_h[ROWS * CDIM];
__device__ float g_qkv[ROWS * QKVDIM];
__device__ float g_attn[ROWS * CDIM];
__device__ float g_x1[ROWS * CDIM];
__device__ float g_fc1[ROWS * HID];
__device__ float g_vt[24 * HDIM * SEQ];   // transposed V: [z][d][seq]

// ---------------- LayerNorm ----------------
__global__ void ln_kernel(const float* __restrict__ x, const float* __restrict__ gam,
                          const float* __restrict__ bet, float* __restrict__ out) {
    __shared__ float red[8];
    const int t = threadIdx.x;
    const float* xr = x + (size_t)blockIdx.x * CDIM;
    float* orow = out + (size_t)blockIdx.x * CDIM;

    float v0 = xr[t], v1 = xr[t + 256], v2 = xr[t + 512];

    float s = v0 + v1 + v2;
#pragma unroll
    for (int o = 16; o; o >>= 1) s += __shfl_xor_sync(~0u, s, o);
    if ((t & 31) == 0) red[t >> 5] = s;
    __syncthreads();
    s = red[0] + red[1] + red[2] + red[3] + red[4] + red[5] + red[6] + red[7];
    const float mu = s * (1.0f / CDIM);
    __syncthreads();

    float d0 = v0 - mu, d1 = v1 - mu, d2 = v2 - mu;
    float q = d0 * d0 + d1 * d1 + d2 * d2;
#pragma unroll
    for (int o = 16; o; o >>= 1) q += __shfl_xor_sync(~0u, q, o);
    if ((t & 31) == 0) red[t >> 5] = q;
    __syncthreads();
    q = red[0] + red[1] + red[2] + red[3] + red[4] + red[5] + red[6] + red[7];
    const float rs = rsqrtf(q * (1.0f / CDIM) + 1e-5f);

    orow[t]       = d0 * rs * gam[t]       + bet[t];
    orow[t + 256] = d1 * rs * gam[t + 256] + bet[t + 256];
    orow[t + 512] = d2 * rs * gam[t + 512] + bet[t + 512];
}

// ---------------- V transpose ----------------
__global__ void transpose_v(const float* __restrict__ qkv, float* __restrict__ vt) {
    __shared__ float tile[32][33];
    const int z = blockIdx.z, b = z / NHEAD, h = z % NHEAD;
    const float* V = qkv + (size_t)b * SEQ * QKVDIM + 2 * CDIM + h * HDIM;
    float* O = vt + (size_t)z * HDIM * SEQ;
    const int k0 = blockIdx.x << 5, n0 = blockIdx.y << 5;
    const int tx = threadIdx.x, ty = threadIdx.y;
#pragma unroll
    for (int i = 0; i < 32; i += 8)
        tile[ty + i][tx] = V[(size_t)(k0 + ty + i) * QKVDIM + n0 + tx];
    __syncthreads();
#pragma unroll
    for (int i = 0; i < 32; i += 8)
        O[(size_t)(n0 + ty + i) * SEQ + k0 + tx] = tile[tx][ty + i];
}

// ---------------- common helpers ----------------
__device__ __forceinline__ void cp16(uint32_t dst, const void* src) {
    asm volatile("cp.async.cg.shared.global [%0], [%1], 16;\n" :: "r"(dst), "l"(src));
}
__device__ __forceinline__ void cp_commit() { asm volatile("cp.async.commit_group;\n"); }

__device__ __forceinline__ void mma8(float* c, const uint32_t* a, const uint32_t* b) {
    asm volatile(
        "mma.sync.aligned.m16n8k8.row.col.f32.tf32.tf32.f32 "
        "{%0,%1,%2,%3}, {%4,%5,%6,%7}, {%8,%9}, {%0,%1,%2,%3};"
        : "+f"(c[0]), "+f"(c[1]), "+f"(c[2]), "+f"(c[3])
        : "r"(a[0]), "r"(a[1]), "r"(a[2]), "r"(a[3]), "r"(b[0]), "r"(b[1]));
}

// swizzled float index within a [rows][32] panel: 16B word c stored at c^(row&7)
__device__ __forceinline__ int swz(int row, int c) {
    return (row << 5) + (((c ^ (row & 7))) << 2);
}

// ---------------- fused flash attention ----------------
// grid: (16 q-tiles, 24 heads), 256 threads. Q tile 128 rows, KV tiles of 64.
// smem (floats): Q[2 panels][128][32] | K[2buf][2p][64][32] | Vt[2buf][2p][64][32] | P[2p][128][32]
__global__ void __launch_bounds__(256, 1)
flash_attn(const float* __restrict__ qkv, const float* __restrict__ vt,
           float* __restrict__ attn) {
    extern __shared__ float fsm[];
    const uint32_t sb = (uint32_t)__cvta_generic_to_shared(fsm);

    const int t = threadIdx.x, lane = t & 31, warp = t >> 5;
    const int lr = lane >> 2, lc = lane & 3;
    const int z = blockIdx.y, b = z / NHEAD, h = z % NHEAD;
    const int m0 = blockIdx.x * 128;

    const float* Qg = qkv + (size_t)b * SEQ * QKVDIM + h * HDIM;
    const float* Kg = qkv + (size_t)b * SEQ * QKVDIM + CDIM + h * HDIM;
    const float* Vg = vt + (size_t)z * HDIM * SEQ;

    // stage Q (2 panels of [128][32])
#pragma unroll
    for (int i = 0; i < 8; i++) {
        const int idx = t + i * 256;
        const int p = idx >> 10, w = idx & 1023;
        const int row = w >> 3, c = w & 7;
        cp16(sb + (uint32_t)(p * 4096 + swz(row, c)) * 4u,
             Qg + (size_t)(m0 + row) * QKVDIM + p * 32 + c * 4);
    }
    auto stage_kv = [&](int j) {
        const int buf = j & 1;
        const int n0 = j * 64;
#pragma unroll
        for (int i = 0; i < 4; i++) {
            const int idx = t + i * 256;
            const int p = idx >> 9, w = idx & 511;
            const int row = w >> 3, c = w & 7;
            cp16(sb + (uint32_t)(8192 + buf * 4096 + p * 2048 + swz(row, c)) * 4u,
                 Kg + (size_t)(n0 + row) * QKVDIM + p * 32 + c * 4);
        }
#pragma unroll
        for (int i = 0; i < 4; i++) {
            const int idx = t + i * 256;
            const int p = idx >> 9, w = idx & 511;
            const int row = w >> 3, c = w & 7;
            cp16(sb + (uint32_t)(16384 + buf * 4096 + p * 2048 + swz(row, c)) * 4u,
                 Vg + (size_t)row * SEQ + n0 + p * 32 + c * 4);
        }
        cp_commit();
    };
    stage_kv(0);   // group 0 = Q + K0 + V0

    float accO[8][4] = {};
    float m_lo = -1e30f, m_hi = -1e30f, l_lo = 0.f, l_hi = 0.f;
    const int r0 = warp * 16 + lr;

    for (int j = 0; j < 32; j++) {
        asm volatile("cp.async.wait_group 0;\n" ::: "memory");
        __syncthreads();
        if (j + 1 < 32) stage_kv(j + 1);

        // ---- S = Q K^T (tile) ----
        float s[8][4] = {};
        const float* kbase = fsm + 8192 + (j & 1) * 4096;
#pragma unroll
        for (int pp = 0; pp < 2; pp++) {
            const uint32_t* qp = (const uint32_t*)(fsm + pp * 4096);
            const uint32_t* kp = (const uint32_t*)(kbase + pp * 2048);
#pragma unroll
            for (int ks = 0; ks < 4; ks++) {
                uint32_t af[4];
                af[0] = qp[swz(r0,     2 * ks)     + lc];
                af[1] = qp[swz(r0 + 8, 2 * ks)     + lc];
                af[2] = qp[swz(r0,     2 * ks + 1) + lc];
                af[3] = qp[swz(r0 + 8, 2 * ks + 1) + lc];
#pragma unroll
                for (int nf = 0; nf < 8; nf++) {
                    uint32_t bf[2];
                    bf[0] = kp[swz(8 * nf + lr, 2 * ks)     + lc];
                    bf[1] = kp[swz(8 * nf + lr, 2 * ks + 1) + lc];
                    mma8(s[nf], af, bf);
                }
            }
        }

        // ---- online softmax ----
        float mx_lo = -1e30f, mx_hi = -1e30f;
#pragma unroll
        for (int nf = 0; nf < 8; nf++) {
#pragma unroll
            for (int k4 = 0; k4 < 4; k4++) s[nf][k4] *= 0.125f;
            mx_lo = fmaxf(mx_lo, fmaxf(s[nf][0], s[nf][1]));
            mx_hi = fmaxf(mx_hi, fmaxf(s[nf][2], s[nf][3]));
        }
        mx_lo = fmaxf(mx_lo, __shfl_xor_sync(~0u, mx_lo, 1));
        mx_lo = fmaxf(mx_lo, __shfl_xor_sync(~0u, mx_lo, 2));
        mx_hi = fmaxf(mx_hi, __shfl_xor_sync(~0u, mx_hi, 1));
        mx_hi = fmaxf(mx_hi, __shfl_xor_sync(~0u, mx_hi, 2));
        const float mn_lo = fmaxf(m_lo, mx_lo), mn_hi = fmaxf(m_hi, mx_hi);
        const float al = __expf(m_lo - mn_lo), ah = __expf(m_hi - mn_hi);
        m_lo = mn_lo; m_hi = mn_hi;

        float rs_lo = 0.f, rs_hi = 0.f;
#pragma unroll
        for (int nf = 0; nf < 8; nf++) {
            s[nf][0] = __expf(s[nf][0] - m_lo);
            s[nf][1] = __expf(s[nf][1] - m_lo);
            s[nf][2] = __expf(s[nf][2] - m_hi);
            s[nf][3] = __expf(s[nf][3] - m_hi);
            rs_lo += s[nf][0] + s[nf][1];
            rs_hi += s[nf][2] + s[nf][3];
        }
        rs_lo += __shfl_xor_sync(~0u, rs_lo, 1);
        rs_lo += __shfl_xor_sync(~0u, rs_lo, 2);
        rs_hi += __shfl_xor_sync(~0u, rs_hi, 1);
        rs_hi += __shfl_xor_sync(~0u, rs_hi, 2);
        l_lo = l_lo * al + rs_lo;
        l_hi = l_hi * ah + rs_hi;
#pragma unroll
        for (int nf = 0; nf < 8; nf++) {
            accO[nf][0] *= al; accO[nf][1] *= al;
            accO[nf][2] *= ah; accO[nf][3] *= ah;
        }

        // ---- store P tile to smem panels ----
        float* P = fsm + 24576;
#pragma unroll
        for (int nf = 0; nf < 8; nf++) {
            const int p = nf >> 2;
            const int w0 = 2 * (nf & 3) + (lc >> 1);
            const int sub = (2 * lc) & 3;
            float* d1 = P + p * 4096 + (r0 << 5) + (((w0 ^ (r0 & 7))) << 2) + sub;
            *(float2*)d1 = make_float2(s[nf][0], s[nf][1]);
            const int r2 = r0 + 8;
            float* d2 = P + p * 4096 + (r2 << 5) + (((w0 ^ (r2 & 7))) << 2) + sub;
            *(float2*)d2 = make_float2(s[nf][2], s[nf][3]);
        }
        __syncthreads();

        // ---- O += P V ----
        const float* vbase = fsm + 16384 + (j & 1) * 4096;
#pragma unroll
        for (int pp = 0; pp < 2; pp++) {
            const uint32_t* ap = (const uint32_t*)(P + pp * 4096);
            const uint32_t* vp = (const uint32_t*)(vbase + pp * 2048);
#pragma unroll
            for (int ks = 0; ks < 4; ks++) {
                uint32_t af[4];
                af[0] = ap[swz(r0,     2 * ks)     + lc];
                af[1] = ap[swz(r0 + 8, 2 * ks)     + lc];
                af[2] = ap[swz(r0,     2 * ks + 1) + lc];
                af[3] = ap[swz(r0 + 8, 2 * ks + 1) + lc];
#pragma unroll
                for (int nf = 0; nf < 8; nf++) {
                    uint32_t bf[2];
                    bf[0] = vp[swz(8 * nf + lr, 2 * ks)     + lc];
                    bf[1] = vp[swz(8 * nf + lr, 2 * ks + 1) + lc];
                    mma8(accO[nf], af, bf);
                }
            }
        }
    }

    // ---- epilogue ----
    const float inv_lo = 1.0f / l_lo, inv_hi = 1.0f / l_hi;
    float* Cb = attn + (size_t)b * SEQ * CDIM + h * HDIM;
    const int m = m0 + r0;
#pragma unroll
    for (int nf = 0; nf < 8; nf++) {
        const int n = 8 * nf + 2 * lc;
        *(float2*)(Cb + (size_t)m * CDIM + n) =
            make_float2(accO[nf][0] * inv_lo, accO[nf][1] * inv_lo);
        *(float2*)(Cb + (size_t)(m + 8) * CDIM + n) =
            make_float2(accO[nf][2] * inv_hi, accO[nf][3] * inv_hi);
    }
}

// ---------------- TF32 tensor-core NT GEMM, cp.async pipeline (round 3) ----------------
template <int EPI, int WARP_M, int WARP_N, int WM_T, int WN_T>
__global__ void __launch_bounds__(WARP_M * WARP_N * 32, 2)
gemm_tc(const float* __restrict__ A, int lda,
        const float* __restrict__ B, int ldb,
        float* __restrict__ C, int ldc, int K,
        const float* __restrict__ bias,
        const float* __restrict__ res) {
    constexpr int NT = WARP_M * WARP_N * 32;
    constexpr int BM = WARP_M * WM_T * 16;
    constexpr int BN = WARP_N * WN_T * 8;
    constexpr int ASZ = BM * 32;
    constexpr int BSZ = BN * 32;
    constexpr int STG = ASZ + BSZ;
    constexpr int NA = ASZ / 4 / NT;
    constexpr int NB = BSZ / 4 / NT;

    extern __shared__ uint32_t smem[];
    const uint32_t smem_b = (uint32_t)__cvta_generic_to_shared(smem);

    const int m0 = blockIdx.y * BM;
    const int n0 = blockIdx.x * BN;
    const int t = threadIdx.x;
    const int lane = t & 31, warp = t >> 5;
    const int wm = warp / WARP_N, wn = warp % WARP_N;
    const int lr = lane >> 2, lc = lane & 3;

    const float* Abase = A + (size_t)m0 * lda;
    const float* Bbase = B + (size_t)n0 * ldb;

    auto issue = [&](int j, int buf) {
        const float* Ak = Abase + j * 32;
        const uint32_t sa = smem_b + (uint32_t)(buf * STG) * 4u;
#pragma unroll
        for (int i = 0; i < NA; i++) {
            const int idx = t + i * NT;
            const int row = idx >> 3, c = idx & 7;
            cp16(sa + (uint32_t)swz(row, c) * 4u, Ak + (size_t)row * lda + c * 4);
        }
        const float* Bk = Bbase + j * 32;
        const uint32_t sbp = smem_b + (uint32_t)(buf * STG + ASZ) * 4u;
#pragma unroll
        for (int i = 0; i < NB; i++) {
            const int idx = t + i * NT;
            const int row = idx >> 3, c = idx & 7;
            cp16(sbp + (uint32_t)swz(row, c) * 4u, Bk + (size_t)row * ldb + c * 4);
        }
        cp_commit();
    };

    const int T = K >> 5;
    issue(0, 0);
    issue(1, 1);

    float acc[WM_T][WN_T][4] = {};
    int buf = 0;

    for (int j = 0; j < T; j++) {
        asm volatile("cp.async.wait_group 1;\n" ::: "memory");
        __syncthreads();
        const uint32_t* a = smem + buf * STG;
        const uint32_t* b = a + ASZ;

#pragma unroll
        for (int ks = 0; ks < 4; ks++) {
            uint32_t af[WM_T][4], bf[WN_T][2];
#pragma unroll
            for (int mt = 0; mt < WM_T; mt++) {
                const int row = (wm * WM_T + mt) * 16 + lr;
                af[mt][0] = a[swz(row,     2 * ks)     + lc];
                af[mt][1] = a[swz(row + 8, 2 * ks)     + lc];
                af[mt][2] = a[swz(row,     2 * ks + 1) + lc];
                af[mt][3] = a[swz(row + 8, 2 * ks + 1) + lc];
            }
#pragma unroll
            for (int nf = 0; nf < WN_T; nf++) {
                const int row = (wn * WN_T + nf) * 8 + lr;
                bf[nf][0] = b[swz(row, 2 * ks)     + lc];
                bf[nf][1] = b[swz(row, 2 * ks + 1) + lc];
            }
#pragma unroll
            for (int mt = 0; mt < WM_T; mt++)
#pragma unroll
                for (int nf = 0; nf < WN_T; nf++)
                    mma8(acc[mt][nf], af[mt], bf[nf]);
        }
        __syncthreads();
        if (j + 2 < T) issue(j + 2, buf);
        else cp_commit();
        buf ^= 1;
    }

#pragma unroll
    for (int mi = 0; mi < WM_T; mi++) {
        const int m = m0 + (wm * WM_T + mi) * 16 + lr;
#pragma unroll
        for (int ni = 0; ni < WN_T; ni++) {
            const int n = n0 + (wn * WN_T + ni) * 8 + (lc << 1);
            float2 bb = make_float2(0.f, 0.f);
            if (EPI != 0) bb = *(const float2*)(bias + n);
#pragma unroll
            for (int half = 0; half < 2; half++) {
                const int mm = m + half * 8;
                float v0 = acc[mi][ni][half * 2 + 0];
                float v1 = acc[mi][ni][half * 2 + 1];
                if (EPI != 0) { v0 += bb.x; v1 += bb.y; }
                if (EPI == 2) {
                    float2 r2 = *(const float2*)(res + (size_t)mm * ldc + n);
                    v0 += r2.x; v1 += r2.y;
                }
                if (EPI == 3) {
                    v0 = 0.5f * v0 * (1.0f + erff(v0 * 0.70710678118654752f));
                    v1 = 0.5f * v1 * (1.0f + erff(v1 * 0.70710678118654752f));
                }
                *(float2*)(C + (size_t)mm * ldc + n) = make_float2(v0, v1);
            }
        }
    }
}

// ---------------- launch ----------------
extern "C" void kernel_launch(void* const* d_in, const int* in_sizes, int n_in,
                              void* d_out, int out_size) {
    const float* x      = (const float*)d_in[0];
    const float* ln1_g  = (const float*)d_in[1];
    const float* ln1_b  = (const float*)d_in[2];
    const float* qkv_w  = (const float*)d_in[3];
    const float* proj_w = (const float*)d_in[4];
    const float* proj_b = (const float*)d_in[5];
    const float* ln2_g  = (const float*)d_in[6];
    const float* ln2_b  = (const float*)d_in[7];
    const float* fc1_w  = (const float*)d_in[8];
    const float* fc1_b  = (const float*)d_in[9];
    const float* fc2_w  = (const float*)d_in[10];
    const float* fc2_b  = (const float*)d_in[11];
    float* out = (float*)d_out;

    float *h, *qkv, *attn, *x1, *fc1, *vt;
    cudaGetSymbolAddress((void**)&h, g_h);
    cudaGetSymbolAddress((void**)&qkv, g_qkv);
    cudaGetSymbolAddress((void**)&attn, g_attn);
    cudaGetSymbolAddress((void**)&x1, g_x1);
    cudaGetSymbolAddress((void**)&fc1, g_fc1);
    cudaGetSymbolAddress((void**)&vt, g_vt);

    constexpr int SM128 = 2 * (128 * 32 + 128 * 32) * 4;  // 64KB
    constexpr int SMFA  = 32768 * 4;                       // 128KB
    cudaFuncSetAttribute(gemm_tc<0, 2, 4, 4, 4>, cudaFuncAttributeMaxDynamicSharedMemorySize, SM128);
    cudaFuncSetAttribute(gemm_tc<2, 2, 4, 4, 4>, cudaFuncAttributeMaxDynamicSharedMemorySize, SM128);
    cudaFuncSetAttribute(gemm_tc<3, 2, 4, 4, 4>, cudaFuncAttributeMaxDynamicSharedMemorySize, SM128);
    cudaFuncSetAttribute(flash_attn, cudaFuncAttributeMaxDynamicSharedMemorySize, SMFA);

    // 1) LN1
    ln_kernel<<<ROWS, 256>>>(x, ln1_g, ln1_b, h);

    // 2) QKV
    gemm_tc<0, 2, 4, 4, 4><<<dim3(QKVDIM / 128, ROWS / 128, 1), 256, SM128>>>(
        h, CDIM, qkv_w, CDIM, qkv, QKVDIM, CDIM, nullptr, nullptr);

    // 3) V transpose + fused flash attention
    transpose_v<<<dim3(SEQ / 32, HDIM / 32, 24), dim3(32, 8)>>>(qkv, vt);
    flash_attn<<<dim3(SEQ / 128, 24), 256, SMFA>>>(qkv, vt, attn);

    // 4) x1 = x + attn @ proj_w^T + proj_b
    gemm_tc<2, 2, 4, 4, 4><<<dim3(CDIM / 128, ROWS / 128, 1), 256, SM128>>>(
        attn, CDIM, proj_w, CDIM, x1, CDIM, CDIM, proj_b, x);

    // 5) LN2
    ln_kernel<<<ROWS, 256>>>(x1, ln2_g, ln2_b, h);

    // 6) fc1 + exact GELU
    gemm_tc<3, 2, 4, 4, 4><<<dim3(HID / 128, ROWS / 128, 1), 256, SM128>>>(
        h, CDIM, fc1_w, CDIM, fc1, HID, CDIM, fc1_b, nullptr);

    // 7) out = x1 + fc1 @ fc2_w^T + fc2_b
    gemm_tc<2, 2, 4, 4, 4><<<dim3(CDIM / 128, ROWS / 128, 1), 256, SM128>>>(
        fc1, HID, fc2_w, HID, out, CDIM, HID, fc2_b, x1);
}